// round 10
// baseline (speedup 1.0000x reference)
#include <cuda_runtime.h>
#include <cuda_bf16.h>

#define TS 64                    // tile side (pixels)
#define MAX_TILES 4096           // (4096/64)^2
#define CAP 512                  // slots per tile (mean ~52 for 200k uniform boxes)
#define BOX_BATCH 4

// Scratch (static zero-init). paint_kernel resets each tile's cursor to 0
// after reading it, so the cursor array is all-zero at the start of every
// call / graph replay — deterministic, no separate zeroing pass needed.
__device__ int g_cursor[MAX_TILES];
__device__ int g_bins[MAX_TILES * CAP];

// ---------------- pass 1: bin boxes into fixed-capacity per-tile lists ----------------
__global__ void __launch_bounds__(256)
scatter_kernel(const float4* __restrict__ boxes,
               const int* __restrict__ wp, const int* __restrict__ hp,
               int n_boxes) {
    int base = (blockIdx.x * blockDim.x + threadIdx.x) * BOX_BATCH;
    if (base >= n_boxes) return;
    const int w = *wp, h = *hp;
    const int tw = (w + TS - 1) / TS;

    float4 b[BOX_BATCH];
#pragma unroll
    for (int k = 0; k < BOX_BATCH; k++)
        if (base + k < n_boxes) b[k] = __ldg(&boxes[base + k]);

#pragma unroll
    for (int k = 0; k < BOX_BATCH; k++) {
        int i = base + k;
        if (i >= n_boxes) continue;
        int cx = (int)(b[k].x * (float)w);
        int cy = (int)(b[k].y * (float)h);
        if (cx < 0 || cx >= w || cy < 0 || cy >= h) continue;

        bool valid = (cx >= 1) & (cx <= w - 2) & (cy >= 1) & (cy <= h - 2);
        if (!valid) {
            int t = (cy / TS) * tw + (cx / TS);
            int slot = atomicAdd(&g_cursor[t], 1);
            if (slot < CAP) g_bins[t * CAP + slot] = i;
        } else {
            int tx0 = (cx - 1) / TS, tx1 = (cx + 1) / TS;
            int ty0 = (cy - 1) / TS, ty1 = (cy + 1) / TS;
            for (int ty = ty0; ty <= ty1; ty++)
                for (int tx = tx0; tx <= tx1; tx++) {
                    int t = ty * tw + tx;
                    int slot = atomicAdd(&g_cursor[t], 1);
                    if (slot < CAP) g_bins[t * CAP + slot] = i;
                }
        }
    }
}

// ---------------- pass 2: per-tile SMEM composite + streamed output ----------------
// One CTA per tile (R5's proven TS=64 paint). Fuses zero-fill + scatter-max +
// sizemap write: the 201 MB output is written exactly once, no global atomics.
__global__ void __launch_bounds__(256)
paint_kernel(const float4* __restrict__ boxes,
             const float* __restrict__ mount,
             const int* __restrict__ wp, const int* __restrict__ hp,
             float* __restrict__ out) {
    __shared__ int s_heat[TS * TS];   // float bits; atomicMax(int) == float max (vals >= 0)
    __shared__ int s_win[TS * TS];    // winner = boxIdx+1 (0 = empty)
    __shared__ int s_cnt;

    const int w = *wp, h = *hp;
    const int tw = (w + TS - 1) / TS, th = (h + TS - 1) / TS;
    const int ntiles = tw * th;
    const int hw = w * h;

    float m[9];
#pragma unroll
    for (int j = 0; j < 9; j++) m[j] = __ldg(&mount[j]);

    for (int t = blockIdx.x; t < ntiles; t += gridDim.x) {
        for (int k = threadIdx.x; k < TS * TS; k += 256) { s_heat[k] = 0; s_win[k] = 0; }
        if (threadIdx.x == 0) {
            int c = g_cursor[t];
            s_cnt = (c < CAP) ? c : CAP;
            g_cursor[t] = 0;               // self-reset scratch for next call
        }
        __syncthreads();

        const int ty = t / tw, tx = t % tw;
        const int x0 = tx * TS, y0 = ty * TS;
        const int cnt = s_cnt;
        const int off = t * CAP;

        for (int j = threadIdx.x; j < cnt; j += 256) {
            int i = g_bins[off + j];
            float4 b = __ldg(&boxes[i]);
            int cx = (int)(b.x * (float)w);
            int cy = (int)(b.y * (float)h);

            // sizemap winner election (center cell in this tile only)
            if (cx / TS == tx && cy / TS == ty)
                atomicMax(&s_win[(cy - y0) * TS + (cx - x0)], i + 1);

            // 3x3 gaussian stamp (only when full window fits in the image)
            if (cx >= 1 && cx <= w - 2 && cy >= 1 && cy <= h - 2) {
#pragma unroll
                for (int dy = -1; dy <= 1; dy++) {
                    int gy = cy + dy - y0;
                    if (gy < 0 || gy >= TS) continue;
#pragma unroll
                    for (int dx = -1; dx <= 1; dx++) {
                        int gx = cx + dx - x0;
                        if (gx < 0 || gx >= TS) continue;
                        atomicMax(&s_heat[gy * TS + gx],
                                  __float_as_int(m[(dy + 1) * 3 + (dx + 1)]));
                    }
                }
            }
        }
        __syncthreads();

        // stream the tile: heat + size0 + size1, float4 coalesced
        for (int idx = threadIdx.x; idx < TS * TS / 4; idx += 256) {
            int row = idx / (TS / 4);
            int c4  = idx % (TS / 4);
            int gy  = y0 + row;
            int gxb = x0 + c4 * 4;
            int soff = row * TS + c4 * 4;

            float4 hv = make_float4(__int_as_float(s_heat[soff + 0]),
                                    __int_as_float(s_heat[soff + 1]),
                                    __int_as_float(s_heat[soff + 2]),
                                    __int_as_float(s_heat[soff + 3]));
            float4 s0 = make_float4(0.f, 0.f, 0.f, 0.f);
            float4 s1 = make_float4(0.f, 0.f, 0.f, 0.f);
#pragma unroll
            for (int q = 0; q < 4; q++) {
                int wv = s_win[soff + q];
                if (wv > 0) {
                    float4 bb = __ldg(&boxes[wv - 1]);
                    ((float*)&s0)[q] = bb.z;
                    ((float*)&s1)[q] = bb.w;
                }
            }
            if (gy < h && gxb + 3 < w) {
                int g = gy * w + gxb;
                *(float4*)(out + g)          = hv;
                *(float4*)(out + hw + g)     = s0;
                *(float4*)(out + 2 * hw + g) = s1;
            } else {
#pragma unroll
                for (int q = 0; q < 4; q++) {
                    int gx = gxb + q;
                    if (gy < h && gx < w) {
                        int g = gy * w + gx;
                        out[g]          = ((float*)&hv)[q];
                        out[hw + g]     = ((float*)&s0)[q];
                        out[2 * hw + g] = ((float*)&s1)[q];
                    }
                }
            }
        }
        __syncthreads();   // protect smem re-zero of next tile iteration
    }
}

extern "C" void kernel_launch(void* const* d_in, const int* in_sizes, int n_in,
                              void* d_out, int out_size) {
    const float4* boxes = (const float4*)d_in[0];  // [N,4] cx,cy,w,h
    const float*  mount = (const float*)d_in[1];   // [3,3]
    const int*    wp    = (const int*)d_in[2];     // scalar w
    const int*    hp    = (const int*)d_in[3];     // scalar h
    float* out = (float*)d_out;                    // [hw heat | hw size0 | hw size1]

    int n_boxes = in_sizes[0] / 4;

    const int threads = 256;
    int n_batched = (n_boxes + BOX_BATCH - 1) / BOX_BATCH;
    int bblocks = (n_batched + threads - 1) / threads;

    scatter_kernel<<<bblocks, threads>>>(boxes, wp, hp, n_boxes);
    paint_kernel<<<MAX_TILES, threads>>>(boxes, mount, wp, hp, out);
}

// round 11
// speedup vs baseline: 1.6011x; 1.6011x over previous
#include <cuda_runtime.h>
#include <cuda_bf16.h>

#define TS 64                    // tile side (pixels)
#define MAX_TILES 4096           // (4096/64)^2
#define CAP 512                  // slots per tile (mean ~52 for 200k uniform boxes)

// Scratch (static zero-init). paint_kernel resets each tile's cursor to 0
// after reading it, so the cursor array is all-zero at the start of every
// call / graph replay — deterministic, no separate zeroing pass needed.
__device__ int  g_cursor[MAX_TILES];
__device__ int2 g_bins[MAX_TILES * CAP];   // {.x = (cy<<16)|cx, .y = boxIdx}

// ---------------- pass 1: bin box payloads into per-tile lists ----------------
__global__ void __launch_bounds__(256)
scatter_kernel(const float4* __restrict__ boxes,
               const int* __restrict__ wp, const int* __restrict__ hp,
               int n_boxes) {
    int i = blockIdx.x * blockDim.x + threadIdx.x;
    if (i >= n_boxes) return;
    const int w = *wp, h = *hp;
    const int tw = (w + TS - 1) / TS;

    float4 b = __ldg(&boxes[i]);
    int cx = (int)(b.x * (float)w);
    int cy = (int)(b.y * (float)h);
    if (cx < 0 || cx >= w || cy < 0 || cy >= h) return;

    int2 e = make_int2((cy << 16) | cx, i);

    bool valid = (cx >= 1) & (cx <= w - 2) & (cy >= 1) & (cy <= h - 2);
    if (!valid) {
        int t = (cy / TS) * tw + (cx / TS);
        int slot = atomicAdd(&g_cursor[t], 1);
        if (slot < CAP) g_bins[t * CAP + slot] = e;
    } else {
        int tx0 = (cx - 1) / TS, tx1 = (cx + 1) / TS;
        int ty0 = (cy - 1) / TS, ty1 = (cy + 1) / TS;
        for (int ty = ty0; ty <= ty1; ty++)
            for (int tx = tx0; tx <= tx1; tx++) {
                int t = ty * tw + tx;
                int slot = atomicAdd(&g_cursor[t], 1);
                if (slot < CAP) g_bins[t * CAP + slot] = e;
            }
    }
}

// ---------------- pass 2: per-tile SMEM composite + streamed output ----------------
// One CTA per tile. Payload bins: composite loop has ZERO dependent global
// loads (cx,cy,idx come straight from the prefetched bin entry).
__global__ void __launch_bounds__(256)
paint_kernel(const float4* __restrict__ boxes,
             const float* __restrict__ mount,
             const int* __restrict__ wp, const int* __restrict__ hp,
             float* __restrict__ out) {
    __shared__ int s_heat[TS * TS];   // float bits; atomicMax(int) == float max (vals >= 0)
    __shared__ int s_win[TS * TS];    // winner = boxIdx+1 (0 = empty)

    const int w = *wp, h = *hp;
    const int tw = (w + TS - 1) / TS, th = (h + TS - 1) / TS;
    const int ntiles = tw * th;
    const int hw = w * h;

    float m[9];
#pragma unroll
    for (int j = 0; j < 9; j++) m[j] = __ldg(&mount[j]);

    for (int t = blockIdx.x; t < ntiles; t += gridDim.x) {
        // ---- prefetch bin entries BEFORE zeroing smem (latency hides under STS) ----
        int c = g_cursor[t];
        const int cnt = (c < CAP) ? c : CAP;
        const int off = t * CAP;
        int2 e0 = make_int2(0, -1), e1 = make_int2(0, -1);
        if ((int)threadIdx.x < cnt)        e0 = g_bins[off + threadIdx.x];
        if ((int)threadIdx.x + 256 < cnt)  e1 = g_bins[off + threadIdx.x + 256];

        for (int k = threadIdx.x; k < TS * TS; k += 256) { s_heat[k] = 0; s_win[k] = 0; }
        if (threadIdx.x == 0) g_cursor[t] = 0;   // self-reset scratch for next call
        __syncthreads();

        const int ty = t / tw, tx = t % tw;
        const int x0 = tx * TS, y0 = ty * TS;

#pragma unroll
        for (int p = 0; p < 2; p++) {
            int2 e = (p == 0) ? e0 : e1;
            if (e.y < 0) continue;
            int cx = e.x & 0xFFFF;
            int cy = e.x >> 16;

            // sizemap winner election (center cell in this tile only)
            if (cx / TS == tx && cy / TS == ty)
                atomicMax(&s_win[(cy - y0) * TS + (cx - x0)], e.y + 1);

            // 3x3 gaussian stamp (only when full window fits in the image)
            if (cx >= 1 && cx <= w - 2 && cy >= 1 && cy <= h - 2) {
#pragma unroll
                for (int dy = -1; dy <= 1; dy++) {
                    int gy = cy + dy - y0;
                    if (gy < 0 || gy >= TS) continue;
#pragma unroll
                    for (int dx = -1; dx <= 1; dx++) {
                        int gx = cx + dx - x0;
                        if (gx < 0 || gx >= TS) continue;
                        atomicMax(&s_heat[gy * TS + gx],
                                  __float_as_int(m[(dy + 1) * 3 + (dx + 1)]));
                    }
                }
            }
        }
        __syncthreads();

        // stream the tile: heat + size0 + size1, float4 coalesced
        for (int idx = threadIdx.x; idx < TS * TS / 4; idx += 256) {
            int row = idx / (TS / 4);
            int c4  = idx % (TS / 4);
            int gy  = y0 + row;
            int gxb = x0 + c4 * 4;
            int soff = row * TS + c4 * 4;

            float4 hv = make_float4(__int_as_float(s_heat[soff + 0]),
                                    __int_as_float(s_heat[soff + 1]),
                                    __int_as_float(s_heat[soff + 2]),
                                    __int_as_float(s_heat[soff + 3]));
            float4 s0 = make_float4(0.f, 0.f, 0.f, 0.f);
            float4 s1 = make_float4(0.f, 0.f, 0.f, 0.f);
#pragma unroll
            for (int q = 0; q < 4; q++) {
                int wv = s_win[soff + q];
                if (wv > 0) {
                    float4 bb = __ldg(&boxes[wv - 1]);   // rare: winner cells only
                    ((float*)&s0)[q] = bb.z;
                    ((float*)&s1)[q] = bb.w;
                }
            }
            if (gy < h && gxb + 3 < w) {
                int g = gy * w + gxb;
                *(float4*)(out + g)          = hv;
                *(float4*)(out + hw + g)     = s0;
                *(float4*)(out + 2 * hw + g) = s1;
            } else {
#pragma unroll
                for (int q = 0; q < 4; q++) {
                    int gx = gxb + q;
                    if (gy < h && gx < w) {
                        int g = gy * w + gx;
                        out[g]          = ((float*)&hv)[q];
                        out[hw + g]     = ((float*)&s0)[q];
                        out[2 * hw + g] = ((float*)&s1)[q];
                    }
                }
            }
        }
        __syncthreads();   // protect smem re-zero of next tile iteration
    }
}

extern "C" void kernel_launch(void* const* d_in, const int* in_sizes, int n_in,
                              void* d_out, int out_size) {
    const float4* boxes = (const float4*)d_in[0];  // [N,4] cx,cy,w,h
    const float*  mount = (const float*)d_in[1];   // [3,3]
    const int*    wp    = (const int*)d_in[2];     // scalar w
    const int*    hp    = (const int*)d_in[3];     // scalar h
    float* out = (float*)d_out;                    // [hw heat | hw size0 | hw size1]

    int n_boxes = in_sizes[0] / 4;

    const int threads = 256;
    int bblocks = (n_boxes + threads - 1) / threads;

    scatter_kernel<<<bblocks, threads>>>(boxes, wp, hp, n_boxes);
    paint_kernel<<<MAX_TILES, threads>>>(boxes, mount, wp, hp, out);
}